// round 7
// baseline (speedup 1.0000x reference)
#include <cuda_runtime.h>
#include <cuda_fp16.h>

#define Bq 4
#define Cc 32
#define Tt 1024
#define Uu 32
#define Hh 128
#define PCH 128                 // half2 pairs per j-chunk (256 j)
#define NCH 4                   // chunks

// Scratch — device globals (no allocations allowed).
__device__ float    g_qp[Bq * Tt * Uu];            // q + bh, (B,T,U) f32
__device__ unsigned g_kh_u[Bq * Uu * Tt / 2];      // k as f16, (B,U,T)
__device__ unsigned g_xh_u[Bq * Cc * Tt / 2];      // x as f16, (B,C,T)
__device__ unsigned g_e_u [Bq * Tt * (Tt / 2)];    // raw scores e as f16, (B,T,T)
__device__ float    g_rm[Bq * Tt];                 // per-row max of e

__device__ __forceinline__ __half2 tanh2(__half2 x) {
    unsigned xi = *reinterpret_cast<unsigned*>(&x), ri;
    asm("tanh.approx.f16x2 %0, %1;" : "=r"(ri) : "r"(xi));
    return *reinterpret_cast<__half2*>(&ri);
}
__device__ __forceinline__ __half2 u2h2(unsigned u) { return *reinterpret_cast<__half2*>(&u); }
__device__ __forceinline__ unsigned h22u(__half2 h) { return *reinterpret_cast<unsigned*>(&h); }

// ---------------------------------------------------------------------------
// k_prep v3: 32 tokens/block, grid = B*(T/32) = 128, 256 threads.
// lane = token, warp w owns u = {w, w+8, w+16, w+24}. x column in registers;
// weights via broadcast LDS. Coalesced kh/xh writes; scattered (cheap) qp.
// ---------------------------------------------------------------------------
__global__ void __launch_bounds__(256) k_prep(const float* __restrict__ x,
                                              const float* __restrict__ Wt,
                                              const float* __restrict__ Wx,
                                              const float* __restrict__ bh) {
    __shared__ float Wts[Cc][33];
    __shared__ float Wxs[Cc][33];
    __shared__ float bhs[Uu];

    int b  = blockIdx.x >> 5;
    int t0 = (blockIdx.x & 31) * 32;
    int tid = threadIdx.x, w = tid >> 5, lane = tid & 31;
    int t = t0 + lane;

    for (int i = tid; i < Cc * Uu; i += 256) {
        int c = i >> 5, u = i & 31;
        Wts[c][u] = Wt[i];
        Wxs[c][u] = Wx[i];
    }
    if (tid < Uu) bhs[tid] = bh[tid];

    // x column in registers (coalesced loads, MLP=32)
    float xcol[Cc];
    #pragma unroll
    for (int c = 0; c < Cc; c++)
        xcol[c] = x[(size_t)b * Cc * Tt + (size_t)c * Tt + t];
    __syncthreads();

    __half* kh = (__half*)g_kh_u;
    __half* xh = (__half*)g_xh_u;

    #pragma unroll
    for (int k = 0; k < 4; k++) {
        int u = w + 8 * k;
        float accq = bhs[u], acck = 0.f;
        #pragma unroll
        for (int c = 0; c < Cc; c++) {
            accq += xcol[c] * Wts[c][u];      // broadcast LDS
            acck += xcol[c] * Wxs[c][u];
        }
        g_qp[((size_t)b * Tt + t) * Uu + u] = accq;                   // scattered (cheap)
        kh[((size_t)b * Uu + u) * Tt + t] = __float2half(acck);       // coalesced
    }

    // xh writes: warp w covers channels {w, w+8, w+16, w+24} (reload x, L1-hot)
    #pragma unroll
    for (int k = 0; k < 4; k++) {
        int c = w + 8 * k;
        xh[((size_t)b * Cc + c) * Tt + t] =
            __float2half(x[(size_t)b * Cc * Tt + (size_t)c * Tt + t]);
    }
}

// ---------------------------------------------------------------------------
// k_scores: hybrid MUFU/poly tanh. 1 row/warp, grid = B*(T/8) = 512, 256 thr.
// ---------------------------------------------------------------------------
__global__ void __launch_bounds__(256, 3) k_scores(const float* __restrict__ Wa,
                                                   const float* __restrict__ ba) {
    __shared__ __half2 khs[Uu][PCH];   // 16KB
    __shared__ __half2 qsm2[8][33];

    int b  = blockIdx.x / (Tt / 8);
    int i0 = (blockIdx.x % (Tt / 8)) * 8;
    int tid = threadIdx.x, w = tid >> 5, lane = tid & 31;
    int i = i0 + w;
    size_t row = (size_t)b * Tt + i;

    qsm2[tid >> 5][tid & 31] =
        __float2half2_rn(g_qp[((size_t)b * Tt + i0 + (tid >> 5)) * Uu + (tid & 31)]);

    __half2 wa2[Uu];
    #pragma unroll
    for (int u = 0; u < Uu; u++) wa2[u] = __float2half2_rn(Wa[u]);
    __half2 ba2  = __float2half2_rn(ba[0]);
    __half2 m2   = __float2half2_rn(-60000.f);
    __half2 z2   = __float2half2_rn(0.f);
    __half2 one2 = __float2half2_rn(1.f);
    __half2 ca2  = __float2half2_rn(-1.f / 3.f);
    __half2 cb2  = __float2half2_rn(2.f / 15.f);

    const uint4* kb4 = (const uint4*)g_kh_u + (size_t)b * (Uu * Tt / 8);
    unsigned* erow = g_e_u + row * (Tt / 2);
    __syncthreads();

    for (int ch = 0; ch < NCH; ch++) {
        __syncthreads();
        #pragma unroll
        for (int k = 0; k < 4; k++) {
            int idx = tid + k * 256;
            int r = idx >> 5, g = idx & 31;
            ((uint4*)khs)[idx] = kb4[r * 128 + ch * 32 + g];
        }
        __syncthreads();

        #pragma unroll
        for (int jt = 0; jt < 4; jt++) {
            int pj = jt * 32 + lane;
            __half2 acc0 = z2, acc1 = z2;
            #pragma unroll
            for (int u = 0; u < Uu; u += 2) {
                __half2 xm = __hadd2(qsm2[w][u], khs[u][pj]);
                acc0 = __hfma2(wa2[u], tanh2(xm), acc0);
                __half2 xp = __hadd2(qsm2[w][u + 1], khs[u + 1][pj]);
                __half2 x2 = __hmul2(xp, xp);
                __half2 tp = __hfma2(x2, cb2, ca2);
                tp = __hfma2(x2, tp, one2);
                acc1 = __hfma2(wa2[u + 1], __hmul2(xp, tp), acc1);
            }
            __half2 e2 = __hadd2(__hadd2(acc0, acc1), ba2);
            m2 = __hmax2(m2, e2);
            erow[ch * PCH + pj] = h22u(e2);
        }
    }

    float m = fmaxf(__low2float(m2), __high2float(m2));
    #pragma unroll
    for (int off = 16; off; off >>= 1)
        m = fmaxf(m, __shfl_xor_sync(0xffffffffu, m, off));
    if (lane == 0) g_rm[row] = m;
}

// ---------------------------------------------------------------------------
// Fused k_av_ff: softmax-apply + LN1 + FF + LN2 + a-write. e-loads pipelined.
// ---------------------------------------------------------------------------
#define OFF_XT   0                          // __half2 xh2s[Cc][256]   32768 B
#define OFF_W1T  32768                      // float W1T[Cc*129]       16512 B
#define OFF_W2P  (OFF_W1T + 16512)          // float W2p[Cc*129]       16512 B
#define OFF_YS   (OFF_W2P + 16512)          // float ys[16*33]          2112 B
#define OFF_H1   (OFF_YS + 2112)            // float h1s[16*132]        8448 B
#define OFF_B1   (OFF_H1 + 8448)            // float b1s[128]            512 B
#define OFF_B2   (OFF_B1 + 512)             // float b2s[32]             128 B
#define OFF_G2   (OFF_B2 + 128)             // float g2s[32]             128 B
#define OFF_BE2  (OFF_G2 + 128)             // float be2s[32]            128 B
#define SMEM_AVFF (OFF_BE2 + 128)           // 77056 B

__global__ void __launch_bounds__(256, 2) k_av_ff(const float* __restrict__ x,
                                                  float* __restrict__ a_out,
                                                  const float* __restrict__ g1,
                                                  const float* __restrict__ be1,
                                                  const float* __restrict__ W1,
                                                  const float* __restrict__ b1,
                                                  const float* __restrict__ W2,
                                                  const float* __restrict__ b2,
                                                  const float* __restrict__ g2,
                                                  const float* __restrict__ be2,
                                                  float* __restrict__ y2) {
    extern __shared__ char dyn[];
    __half2 (*xh2s)[256] = (__half2 (*)[256])(dyn + OFF_XT);
    float* W1T  = (float*)(dyn + OFF_W1T);
    float* W2p  = (float*)(dyn + OFF_W2P);
    float* ys   = (float*)(dyn + OFF_YS);
    float* h1s  = (float*)(dyn + OFF_H1);
    float* b1s  = (float*)(dyn + OFF_B1);
    float* b2s  = (float*)(dyn + OFF_B2);
    float* g2s  = (float*)(dyn + OFF_G2);
    float* be2s = (float*)(dyn + OFF_BE2);

    int b  = blockIdx.x / (Tt / 16);
    int t0 = (blockIdx.x % (Tt / 16)) * 16;
    int tid = threadIdx.x, w = tid >> 5, lane = tid & 31;
    int tA = t0 + 2 * w, tB = tA + 1;
    size_t rowA = (size_t)b * Tt + tA, rowB = rowA + 1;

    for (int i = tid; i < Hh * Cc; i += 256) {
        int h = i >> 5, c = i & 31;
        W1T[c * 129 + h] = W1[i];
        int c2 = i >> 7, h2 = i & 127;
        W2p[c2 * 129 + h2] = W2[i];
    }
    if (tid < Hh) b1s[tid] = b1[tid];
    if (tid < Cc) { b2s[tid] = b2[tid]; g2s[tid] = g2[tid]; be2s[tid] = be2[tid]; }

    const unsigned* eAu = g_e_u + rowA * (Tt / 2);
    const unsigned* eBu = g_e_u + rowB * (Tt / 2);
    const uint4* eA4 = (const uint4*)eAu;
    const uint4* eB4 = (const uint4*)eBu;

    float sA = 0.f, sB = 0.f;
    __half2 zero2 = __float2half2_rn(0.f);
    __half2 vA[Cc], vB[Cc];
    #pragma unroll
    for (int c = 0; c < Cc; c++) { vA[c] = zero2; vB[c] = zero2; }

    // ---- software-pipelined e loads ----
    uint4 eaCur = eA4[lane], ebCur = eB4[lane];

    for (int chunk = 0; chunk < 2; chunk++) {
        __syncthreads();
        for (int idx = tid; idx < Cc * 64; idx += 256) {
            int c = idx >> 6, g = idx & 63;
            ((uint4*)xh2s)[c * 64 + g] =
                ((const uint4*)g_xh_u)[(size_t)b * Cc * Tt / 8 + c * 128 + chunk * 64 + g];
        }
        __syncthreads();

        #pragma unroll
        for (int q = 0; q < 2; q++) {
            int lp4 = q * 32 + lane;
            uint4 ea = eaCur, eb = ebCur;
            int gn = chunk * 64 + q * 32 + 32 + lane;   // next q-iter's index
            if (gn < 128) { eaCur = eA4[gn]; ebCur = eB4[gn]; }

            unsigned eua[4] = {ea.x, ea.y, ea.z, ea.w};
            unsigned eub[4] = {eb.x, eb.y, eb.z, eb.w};
            __half2 pA[4], pB[4];
            #pragma unroll
            for (int r = 0; r < 4; r++) {
                float2 fa = __half22float2(u2h2(eua[r]));
                float2 fb = __half22float2(u2h2(eub[r]));
                float pax = __expf(fa.x), pay = __expf(fa.y);
                float pbx = __expf(fb.x), pby = __expf(fb.y);
                sA += pax + pay; sB += pbx + pby;
                pA[r] = __floats2half2_rn(pax, pay);
                pB[r] = __floats2half2_rn(pbx, pby);
            }
            #pragma unroll
            for (int c = 0; c < Cc; c++) {
                uint4 xv = ((const uint4*)&xh2s[c][0])[lp4];
                vA[c] = __hfma2(pA[0], u2h2(xv.x), vA[c]);
                vA[c] = __hfma2(pA[1], u2h2(xv.y), vA[c]);
                vA[c] = __hfma2(pA[2], u2h2(xv.z), vA[c]);
                vA[c] = __hfma2(pA[3], u2h2(xv.w), vA[c]);
                vB[c] = __hfma2(pB[0], u2h2(xv.x), vB[c]);
                vB[c] = __hfma2(pB[1], u2h2(xv.y), vB[c]);
                vB[c] = __hfma2(pB[2], u2h2(xv.z), vB[c]);
                vB[c] = __hfma2(pB[3], u2h2(xv.w), vB[c]);
            }
        }
    }

    float vfA[Cc], vfB[Cc];
    #pragma unroll
    for (int c = 0; c < Cc; c++) {
        float2 fa = __half22float2(vA[c]); vfA[c] = fa.x + fa.y;
        float2 fb = __half22float2(vB[c]); vfB[c] = fb.x + fb.y;
    }

    #pragma unroll
    for (int off = 16; off; off >>= 1) {
        sA += __shfl_xor_sync(0xffffffffu, sA, off);
        sB += __shfl_xor_sync(0xffffffffu, sB, off);
    }
    float invA = 1.f / (sA + 1e-5f * __expf(g_rm[rowA]));
    float invB = 1.f / (sB + 1e-5f * __expf(g_rm[rowB]));

    float mineA = 0.f, mineB = 0.f;
    #pragma unroll
    for (int c = 0; c < Cc; c++) {
        float ta = vfA[c], tb = vfB[c];
        #pragma unroll
        for (int off = 16; off; off >>= 1) {
            ta += __shfl_xor_sync(0xffffffffu, ta, off);
            tb += __shfl_xor_sync(0xffffffffu, tb, off);
        }
        if (lane == c) { mineA = ta; mineB = tb; }
    }

    const float* xb = x + (size_t)b * Cc * Tt + (size_t)lane * Tt;
    #pragma unroll
    for (int r = 0; r < 2; r++) {
        int t = (r == 0) ? tA : tB;
        float z = xb[t] + ((r == 0) ? mineA * invA : mineB * invB);
        float sum = z;
        #pragma unroll
        for (int off = 16; off; off >>= 1)
            sum += __shfl_xor_sync(0xffffffffu, sum, off);
        float mean = sum * (1.f / Cc);
        float d = z - mean;
        float vv = d * d;
        #pragma unroll
        for (int off = 16; off; off >>= 1)
            vv += __shfl_xor_sync(0xffffffffu, vv, off);
        float rstd = rsqrtf(vv * (1.f / Cc) + 1e-14f);
        ys[(2 * w + r) * 33 + lane] = d * rstd * g1[lane] + be1[lane];
    }
    __syncwarp();

    int tokbase = 2 * w;
    float acc[4][2];
    #pragma unroll
    for (int k = 0; k < 4; k++) {
        float bb = b1s[lane + 32 * k];
        acc[k][0] = bb; acc[k][1] = bb;
    }
    #pragma unroll
    for (int c = 0; c < Cc; c++) {
        float yv0 = ys[tokbase * 33 + c];
        float yv1 = ys[(tokbase + 1) * 33 + c];
        #pragma unroll
        for (int k = 0; k < 4; k++) {
            float wv = W1T[c * 129 + lane + 32 * k];
            acc[k][0] += yv0 * wv;
            acc[k][1] += yv1 * wv;
        }
    }
    #pragma unroll
    for (int k = 0; k < 4; k++) {
        h1s[tokbase * 132 + lane + 32 * k]       = fmaxf(acc[k][0], 0.f);
        h1s[(tokbase + 1) * 132 + lane + 32 * k] = fmaxf(acc[k][1], 0.f);
    }
    __syncwarp();

    float a2[2] = {0.f, 0.f};
    #pragma unroll 4
    for (int h = 0; h < Hh; h++) {
        float wv = W2p[lane * 129 + h];
        a2[0] += h1s[tokbase * 132 + h] * wv;
        a2[1] += h1s[(tokbase + 1) * 132 + h] * wv;
    }

    #pragma unroll
    for (int tk = 0; tk < 2; tk++) {
        int tok = tokbase + tk;
        int t = t0 + tok;
        float z = ys[tok * 33 + lane] + a2[tk] + b2s[lane];
        float sum = z;
        #pragma unroll
        for (int off = 16; off; off >>= 1)
            sum += __shfl_xor_sync(0xffffffffu, sum, off);
        float mean = sum * (1.f / Cc);
        float d = z - mean;
        float vv = d * d;
        #pragma unroll
        for (int off = 16; off; off >>= 1)
            vv += __shfl_xor_sync(0xffffffffu, vv, off);
        float rstd = rsqrtf(vv * (1.f / Cc) + 1e-14f);
        y2[(size_t)b * Cc * Tt + (size_t)lane * Tt + t] = d * rstd * g2s[lane] + be2s[lane];
    }

    float* arowA = a_out + rowA * Tt;
    float* arowB = a_out + rowB * Tt;
    #pragma unroll
    for (int q = 0; q < 16; q++) {
        int idx = q * 32 + lane;
        float2 fa = __half22float2(u2h2(eAu[idx]));
        float2 fb = __half22float2(u2h2(eBu[idx]));
        ((float2*)arowA)[idx] = make_float2(__expf(fa.x) * invA, __expf(fa.y) * invA);
        ((float2*)arowB)[idx] = make_float2(__expf(fb.x) * invB, __expf(fb.y) * invB);
    }
}

// ---------------------------------------------------------------------------
extern "C" void kernel_launch(void* const* d_in, const int* in_sizes, int n_in,
                              void* d_out, int out_size) {
    (void)in_sizes; (void)n_in; (void)out_size;
    const float* x   = (const float*)d_in[0];
    const float* Wt  = (const float*)d_in[1];
    const float* Wx  = (const float*)d_in[2];
    const float* bh  = (const float*)d_in[3];
    const float* Wa  = (const float*)d_in[4];
    const float* ba  = (const float*)d_in[5];
    const float* g1  = (const float*)d_in[6];
    const float* be1 = (const float*)d_in[7];
    const float* W1  = (const float*)d_in[8];
    const float* b1  = (const float*)d_in[9];
    const float* W2  = (const float*)d_in[10];
    const float* b2  = (const float*)d_in[11];
    const float* g2  = (const float*)d_in[12];
    const float* be2 = (const float*)d_in[13];

    float* out = (float*)d_out;
    float* y2  = out;                    // (B,C,T) = 131072 floats
    float* a   = out + Bq * Cc * Tt;     // (B,T,T) = 4194304 floats

    cudaFuncSetAttribute(k_av_ff, cudaFuncAttributeMaxDynamicSharedMemorySize, SMEM_AVFF);

    k_prep  <<<Bq * (Tt / 32), 256>>>(x, Wt, Wx, bh);
    k_scores<<<Bq * (Tt / 8),  256>>>(Wa, ba);
    k_av_ff <<<Bq * (Tt / 16), 256, SMEM_AVFF>>>(x, a, g1, be1, W1, b1, W2, b2, g2, be2, y2);
}

// round 8
// speedup vs baseline: 1.0478x; 1.0478x over previous
#include <cuda_runtime.h>
#include <cuda_fp16.h>

#define Bq 4
#define Cc 32
#define Tt 1024
#define Uu 32
#define Hh 128
#define PCH 128                 // half2 pairs per j-chunk (256 j)
#define NCH 4                   // chunks

// Scratch — device globals (no allocations allowed).
__device__ float    g_qp[Bq * Tt * Uu];            // q + bh, (B,T,U) f32
__device__ unsigned g_kh_u[Bq * Uu * Tt / 2];      // k as f16, (B,U,T)
__device__ unsigned g_xh_u[Bq * Cc * Tt / 2];      // x as f16, (B,C,T)
__device__ unsigned g_e_u [Bq * Tt * (Tt / 2)];    // raw scores e as f16, (B,T,T)
__device__ float    g_rm[Bq * Tt];                 // per-row max of e

__device__ __forceinline__ __half2 tanh2(__half2 x) {
    unsigned xi = *reinterpret_cast<unsigned*>(&x), ri;
    asm("tanh.approx.f16x2 %0, %1;" : "=r"(ri) : "r"(xi));
    return *reinterpret_cast<__half2*>(&ri);
}
__device__ __forceinline__ __half2 u2h2(unsigned u) { return *reinterpret_cast<__half2*>(&u); }
__device__ __forceinline__ unsigned h22u(__half2 h) { return *reinterpret_cast<unsigned*>(&h); }

// ---------------------------------------------------------------------------
// k_prep v4: 8 tokens/block, grid = B*(T/8) = 512 blocks, 256 threads.
// warp = token (x via broadcast LDS), lane = u (weight row, conflict-free).
// 64 FMA/thread; ~10 live regs — no spill. Coalesced qp; packed kh/xh writes.
// ---------------------------------------------------------------------------
__global__ void __launch_bounds__(256) k_prep(const float* __restrict__ x,
                                              const float* __restrict__ Wt,
                                              const float* __restrict__ Wx,
                                              const float* __restrict__ bh) {
    __shared__ float xs[Cc][9];        // x tile: 32c x 8t (pad 9)
    __shared__ float Wts[Cc][33];
    __shared__ float Wxs[Cc][33];
    __shared__ float bhs[Uu];
    __shared__ __half kts[Uu][10];     // k f16 tile (pad 10)

    int b  = blockIdx.x >> 7;
    int t0 = (blockIdx.x & 127) * 8;
    int tid = threadIdx.x, w = tid >> 5, lane = tid & 31;

    // stage x tile: 256 floats
    {
        int c = tid >> 3, tl = tid & 7;
        xs[c][tl] = x[(size_t)b * Cc * Tt + (size_t)c * Tt + t0 + tl];
    }
    // stage weights: 2x1024 floats (L2-hot after first wave)
    for (int i = tid; i < Cc * Uu; i += 256) {
        int c = i >> 5, u = i & 31;
        Wts[c][u] = Wt[i];
        Wxs[c][u] = Wx[i];
    }
    if (tid < Uu) bhs[tid] = bh[tid];
    __syncthreads();

    {   // warp w = token t0+w; lane = u
        int tl = w, u = lane;
        float accq = bhs[u], acck = 0.f;
        #pragma unroll
        for (int c = 0; c < Cc; c++) {
            float xv = xs[c][tl];              // broadcast (N=1)
            accq += xv * Wts[c][u];            // row read, conflict-free
            acck += xv * Wxs[c][u];
        }
        g_qp[((size_t)b * Tt + t0 + tl) * Uu + u] = accq;   // 128B coalesced/warp
        kts[u][tl] = __float2half(acck);
    }
    __syncthreads();

    // packed writes: kh rows (from kts) and xh rows (from xs), uint each
    if (tid < 128) {
        int r = tid >> 2, g = tid & 3;         // 32 rows x 4 uint-groups
        __half* kh = (__half*)g_kh_u;
        __half2 kv = __halves2half2(kts[r][2 * g], kts[r][2 * g + 1]);
        *(unsigned*)(kh + ((size_t)b * Uu + r) * Tt + t0 + 2 * g) = h22u(kv);
        __half* xh = (__half*)g_xh_u;
        __half2 xv = __floats2half2_rn(xs[r][2 * g], xs[r][2 * g + 1]);
        *(unsigned*)(xh + ((size_t)b * Cc + r) * Tt + t0 + 2 * g) = h22u(xv);
    }
}

// ---------------------------------------------------------------------------
// k_scores: hybrid MUFU/poly tanh. 1 row/warp, grid = B*(T/8) = 512, 256 thr.
// Even u -> tanh.approx.f16x2 (MUFU); odd u -> degree-5 poly (FMA pipe).
// ---------------------------------------------------------------------------
__global__ void __launch_bounds__(256, 3) k_scores(const float* __restrict__ Wa,
                                                   const float* __restrict__ ba) {
    __shared__ __half2 khs[Uu][PCH];   // 16KB
    __shared__ __half2 qsm2[8][33];

    int b  = blockIdx.x / (Tt / 8);
    int i0 = (blockIdx.x % (Tt / 8)) * 8;
    int tid = threadIdx.x, w = tid >> 5, lane = tid & 31;
    int i = i0 + w;
    size_t row = (size_t)b * Tt + i;

    qsm2[tid >> 5][tid & 31] =
        __float2half2_rn(g_qp[((size_t)b * Tt + i0 + (tid >> 5)) * Uu + (tid & 31)]);

    __half2 wa2[Uu];
    #pragma unroll
    for (int u = 0; u < Uu; u++) wa2[u] = __float2half2_rn(Wa[u]);
    __half2 ba2  = __float2half2_rn(ba[0]);
    __half2 m2   = __float2half2_rn(-60000.f);
    __half2 z2   = __float2half2_rn(0.f);
    __half2 one2 = __float2half2_rn(1.f);
    __half2 ca2  = __float2half2_rn(-1.f / 3.f);
    __half2 cb2  = __float2half2_rn(2.f / 15.f);

    const uint4* kb4 = (const uint4*)g_kh_u + (size_t)b * (Uu * Tt / 8);
    unsigned* erow = g_e_u + row * (Tt / 2);
    __syncthreads();

    for (int ch = 0; ch < NCH; ch++) {
        __syncthreads();
        #pragma unroll
        for (int k = 0; k < 4; k++) {
            int idx = tid + k * 256;
            int r = idx >> 5, g = idx & 31;
            ((uint4*)khs)[idx] = kb4[r * 128 + ch * 32 + g];
        }
        __syncthreads();

        #pragma unroll
        for (int jt = 0; jt < 4; jt++) {
            int pj = jt * 32 + lane;
            __half2 acc0 = z2, acc1 = z2;
            #pragma unroll
            for (int u = 0; u < Uu; u += 2) {
                __half2 xm = __hadd2(qsm2[w][u], khs[u][pj]);
                acc0 = __hfma2(wa2[u], tanh2(xm), acc0);
                __half2 xp = __hadd2(qsm2[w][u + 1], khs[u + 1][pj]);
                __half2 x2 = __hmul2(xp, xp);
                __half2 tp = __hfma2(x2, cb2, ca2);
                tp = __hfma2(x2, tp, one2);
                acc1 = __hfma2(wa2[u + 1], __hmul2(xp, tp), acc1);
            }
            __half2 e2 = __hadd2(__hadd2(acc0, acc1), ba2);
            m2 = __hmax2(m2, e2);
            erow[ch * PCH + pj] = h22u(e2);
        }
    }

    float m = fmaxf(__low2float(m2), __high2float(m2));
    #pragma unroll
    for (int off = 16; off; off >>= 1)
        m = fmaxf(m, __shfl_xor_sync(0xffffffffu, m, off));
    if (lane == 0) g_rm[row] = m;
}

// ---------------------------------------------------------------------------
// Fused k_av_ff (R6 known-good): softmax-apply + LN1 + FF + LN2 + a-write.
// ---------------------------------------------------------------------------
#define OFF_XT   0                          // __half2 xh2s[Cc][256]   32768 B
#define OFF_W1T  32768                      // float W1T[Cc*129]       16512 B
#define OFF_W2P  (OFF_W1T + 16512)          // float W2p[Cc*129]       16512 B
#define OFF_YS   (OFF_W2P + 16512)          // float ys[16*33]          2112 B
#define OFF_H1   (OFF_YS + 2112)            // float h1s[16*132]        8448 B
#define OFF_B1   (OFF_H1 + 8448)            // float b1s[128]            512 B
#define OFF_B2   (OFF_B1 + 512)             // float b2s[32]             128 B
#define OFF_G2   (OFF_B2 + 128)             // float g2s[32]             128 B
#define OFF_BE2  (OFF_G2 + 128)             // float be2s[32]            128 B
#define SMEM_AVFF (OFF_BE2 + 128)           // 77056 B

__global__ void __launch_bounds__(256) k_av_ff(const float* __restrict__ x,
                                               float* __restrict__ a_out,
                                               const float* __restrict__ g1,
                                               const float* __restrict__ be1,
                                               const float* __restrict__ W1,
                                               const float* __restrict__ b1,
                                               const float* __restrict__ W2,
                                               const float* __restrict__ b2,
                                               const float* __restrict__ g2,
                                               const float* __restrict__ be2,
                                               float* __restrict__ y2) {
    extern __shared__ char dyn[];
    __half2 (*xh2s)[256] = (__half2 (*)[256])(dyn + OFF_XT);
    float* W1T  = (float*)(dyn + OFF_W1T);
    float* W2p  = (float*)(dyn + OFF_W2P);
    float* ys   = (float*)(dyn + OFF_YS);
    float* h1s  = (float*)(dyn + OFF_H1);
    float* b1s  = (float*)(dyn + OFF_B1);
    float* b2s  = (float*)(dyn + OFF_B2);
    float* g2s  = (float*)(dyn + OFF_G2);
    float* be2s = (float*)(dyn + OFF_BE2);

    int b  = blockIdx.x / (Tt / 16);
    int t0 = (blockIdx.x % (Tt / 16)) * 16;
    int tid = threadIdx.x, w = tid >> 5, lane = tid & 31;
    int tA = t0 + 2 * w, tB = tA + 1;
    size_t rowA = (size_t)b * Tt + tA, rowB = rowA + 1;

    for (int i = tid; i < Hh * Cc; i += 256) {
        int h = i >> 5, c = i & 31;
        W1T[c * 129 + h] = W1[i];
        int c2 = i >> 7, h2 = i & 127;
        W2p[c2 * 129 + h2] = W2[i];
    }
    if (tid < Hh) b1s[tid] = b1[tid];
    if (tid < Cc) { b2s[tid] = b2[tid]; g2s[tid] = g2[tid]; be2s[tid] = be2[tid]; }

    const unsigned* eAu = g_e_u + rowA * (Tt / 2);
    const unsigned* eBu = g_e_u + rowB * (Tt / 2);
    const uint4* eA4 = (const uint4*)eAu;
    const uint4* eB4 = (const uint4*)eBu;

    float sA = 0.f, sB = 0.f;
    __half2 zero2 = __float2half2_rn(0.f);
    __half2 vA[Cc], vB[Cc];
    #pragma unroll
    for (int c = 0; c < Cc; c++) { vA[c] = zero2; vB[c] = zero2; }

    for (int chunk = 0; chunk < 2; chunk++) {
        __syncthreads();
        for (int idx = tid; idx < Cc * 64; idx += 256) {
            int c = idx >> 6, g = idx & 63;
            ((uint4*)xh2s)[c * 64 + g] =
                ((const uint4*)g_xh_u)[(size_t)b * Cc * Tt / 8 + c * 128 + chunk * 64 + g];
        }
        __syncthreads();

        #pragma unroll
        for (int q = 0; q < 2; q++) {
            int g   = chunk * 64 + q * 32 + lane;
            int lp4 = q * 32 + lane;
            uint4 ea = eA4[g], eb = eB4[g];
            unsigned eua[4] = {ea.x, ea.y, ea.z, ea.w};
            unsigned eub[4] = {eb.x, eb.y, eb.z, eb.w};
            __half2 pA[4], pB[4];
            #pragma unroll
            for (int r = 0; r < 4; r++) {
                float2 fa = __half22float2(u2h2(eua[r]));
                float2 fb = __half22float2(u2h2(eub[r]));
                float pax = __expf(fa.x), pay = __expf(fa.y);
                float pbx = __expf(fb.x), pby = __expf(fb.y);
                sA += pax + pay; sB += pbx + pby;
                pA[r] = __floats2half2_rn(pax, pay);
                pB[r] = __floats2half2_rn(pbx, pby);
            }
            #pragma unroll
            for (int c = 0; c < Cc; c++) {
                uint4 xv = ((const uint4*)&xh2s[c][0])[lp4];
                vA[c] = __hfma2(pA[0], u2h2(xv.x), vA[c]);
                vA[c] = __hfma2(pA[1], u2h2(xv.y), vA[c]);
                vA[c] = __hfma2(pA[2], u2h2(xv.z), vA[c]);
                vA[c] = __hfma2(pA[3], u2h2(xv.w), vA[c]);
                vB[c] = __hfma2(pB[0], u2h2(xv.x), vB[c]);
                vB[c] = __hfma2(pB[1], u2h2(xv.y), vB[c]);
                vB[c] = __hfma2(pB[2], u2h2(xv.z), vB[c]);
                vB[c] = __hfma2(pB[3], u2h2(xv.w), vB[c]);
            }
        }
    }

    float vfA[Cc], vfB[Cc];
    #pragma unroll
    for (int c = 0; c < Cc; c++) {
        float2 fa = __half22float2(vA[c]); vfA[c] = fa.x + fa.y;
        float2 fb = __half22float2(vB[c]); vfB[c] = fb.x + fb.y;
    }

    #pragma unroll
    for (int off = 16; off; off >>= 1) {
        sA += __shfl_xor_sync(0xffffffffu, sA, off);
        sB += __shfl_xor_sync(0xffffffffu, sB, off);
    }
    float invA = 1.f / (sA + 1e-5f * __expf(g_rm[rowA]));
    float invB = 1.f / (sB + 1e-5f * __expf(g_rm[rowB]));

    float mineA = 0.f, mineB = 0.f;
    #pragma unroll
    for (int c = 0; c < Cc; c++) {
        float ta = vfA[c], tb = vfB[c];
        #pragma unroll
        for (int off = 16; off; off >>= 1) {
            ta += __shfl_xor_sync(0xffffffffu, ta, off);
            tb += __shfl_xor_sync(0xffffffffu, tb, off);
        }
        if (lane == c) { mineA = ta; mineB = tb; }
    }

    const float* xb = x + (size_t)b * Cc * Tt + (size_t)lane * Tt;
    #pragma unroll
    for (int r = 0; r < 2; r++) {
        int t = (r == 0) ? tA : tB;
        float z = xb[t] + ((r == 0) ? mineA * invA : mineB * invB);
        float sum = z;
        #pragma unroll
        for (int off = 16; off; off >>= 1)
            sum += __shfl_xor_sync(0xffffffffu, sum, off);
        float mean = sum * (1.f / Cc);
        float d = z - mean;
        float vv = d * d;
        #pragma unroll
        for (int off = 16; off; off >>= 1)
            vv += __shfl_xor_sync(0xffffffffu, vv, off);
        float rstd = rsqrtf(vv * (1.f / Cc) + 1e-14f);
        ys[(2 * w + r) * 33 + lane] = d * rstd * g1[lane] + be1[lane];
    }
    __syncwarp();

    int tokbase = 2 * w;
    float acc[4][2];
    #pragma unroll
    for (int k = 0; k < 4; k++) {
        float bb = b1s[lane + 32 * k];
        acc[k][0] = bb; acc[k][1] = bb;
    }
    #pragma unroll
    for (int c = 0; c < Cc; c++) {
        float yv0 = ys[tokbase * 33 + c];
        float yv1 = ys[(tokbase + 1) * 33 + c];
        #pragma unroll
        for (int k = 0; k < 4; k++) {
            float wv = W1T[c * 129 + lane + 32 * k];
            acc[k][0] += yv0 * wv;
            acc[k][1] += yv1 * wv;
        }
    }
    #pragma unroll
    for (int k = 0; k < 4; k++) {
        h1s[tokbase * 132 + lane + 32 * k]       = fmaxf(acc[k][0], 0.f);
        h1s[(tokbase + 1) * 132 + lane + 32 * k] = fmaxf(acc[k][1], 0.f);
    }
    __syncwarp();

    float a2[2] = {0.f, 0.f};
    #pragma unroll 4
    for (int h = 0; h < Hh; h++) {
        float wv = W2p[lane * 129 + h];
        a2[0] += h1s[tokbase * 132 + h] * wv;
        a2[1] += h1s[(tokbase + 1) * 132 + h] * wv;
    }

    #pragma unroll
    for (int tk = 0; tk < 2; tk++) {
        int tok = tokbase + tk;
        int t = t0 + tok;
        float z = ys[tok * 33 + lane] + a2[tk] + b2s[lane];
        float sum = z;
        #pragma unroll
        for (int off = 16; off; off >>= 1)
            sum += __shfl_xor_sync(0xffffffffu, sum, off);
        float mean = sum * (1.f / Cc);
        float d = z - mean;
        float vv = d * d;
        #pragma unroll
        for (int off = 16; off; off >>= 1)
            vv += __shfl_xor_sync(0xffffffffu, vv, off);
        float rstd = rsqrtf(vv * (1.f / Cc) + 1e-14f);
        y2[(size_t)b * Cc * Tt + (size_t)lane * Tt + t] = d * rstd * g2s[lane] + be2s[lane];
    }

    float* arowA = a_out + rowA * Tt;
    float* arowB = a_out + rowB * Tt;
    #pragma unroll
    for (int q = 0; q < 16; q++) {
        int idx = q * 32 + lane;
        float2 fa = __half22float2(u2h2(eAu[idx]));
        float2 fb = __half22float2(u2h2(eBu[idx]));
        ((float2*)arowA)[idx] = make_float2(__expf(fa.x) * invA, __expf(fa.y) * invA);
        ((float2*)arowB)[idx] = make_float2(__expf(fb.x) * invB, __expf(fb.y) * invB);
    }
}

// ---------------------------------------------------------------------------
extern "C" void kernel_launch(void* const* d_in, const int* in_sizes, int n_in,
                              void* d_out, int out_size) {
    (void)in_sizes; (void)n_in; (void)out_size;
    const float* x   = (const float*)d_in[0];
    const float* Wt  = (const float*)d_in[1];
    const float* Wx  = (const float*)d_in[2];
    const float* bh  = (const float*)d_in[3];
    const float* Wa  = (const float*)d_in[4];
    const float* ba  = (const float*)d_in[5];
    const float* g1  = (const float*)d_in[6];
    const float* be1 = (const float*)d_in[7];
    const float* W1  = (const float*)d_in[8];
    const float* b1  = (const float*)d_in[9];
    const float* W2  = (const float*)d_in[10];
    const float* b2  = (const float*)d_in[11];
    const float* g2  = (const float*)d_in[12];
    const float* be2 = (const float*)d_in[13];

    float* out = (float*)d_out;
    float* y2  = out;                    // (B,C,T) = 131072 floats
    float* a   = out + Bq * Cc * Tt;     // (B,T,T) = 4194304 floats

    cudaFuncSetAttribute(k_av_ff, cudaFuncAttributeMaxDynamicSharedMemorySize, SMEM_AVFF);

    k_prep  <<<Bq * (Tt / 8),  256>>>(x, Wt, Wx, bh);
    k_scores<<<Bq * (Tt / 8),  256>>>(Wa, ba);
    k_av_ff <<<Bq * (Tt / 16), 256, SMEM_AVFF>>>(x, a, g1, be1, W1, b1, W2, b2, g2, be2, y2);
}

// round 9
// speedup vs baseline: 1.0512x; 1.0033x over previous
#include <cuda_runtime.h>
#include <cuda_fp16.h>

#define Bq 4
#define Cc 32
#define Tt 1024
#define Uu 32
#define Hh 128
#define PCH 128                 // half2 pairs per j-chunk (256 j)
#define NCH 4                   // chunks

// Scratch — device globals (no allocations allowed).
__device__ float    g_qp[Bq * Tt * Uu];            // q + bh, (B,T,U) f32
__device__ unsigned g_kh_u[Bq * Uu * Tt / 2];      // k as f16, (B,U,T)
__device__ unsigned g_xh_u[Bq * Cc * Tt / 2];      // x as f16, (B,C,T)
__device__ unsigned g_e_u [Bq * Tt * (Tt / 2)];    // raw scores e as f16, (B,T,T)
__device__ float    g_rm[Bq * Tt];                 // per-row max of e

__device__ __forceinline__ __half2 tanh2(__half2 x) {
    unsigned xi = *reinterpret_cast<unsigned*>(&x), ri;
    asm("tanh.approx.f16x2 %0, %1;" : "=r"(ri) : "r"(xi));
    return *reinterpret_cast<__half2*>(&ri);
}
__device__ __forceinline__ __half2 u2h2(unsigned u) { return *reinterpret_cast<__half2*>(&u); }
__device__ __forceinline__ unsigned h22u(__half2 h) { return *reinterpret_cast<unsigned*>(&h); }

// ---------------------------------------------------------------------------
// k_prep (R8): 8 tokens/block, grid = B*(T/8) = 512 blocks, 256 threads.
// ---------------------------------------------------------------------------
__global__ void __launch_bounds__(256) k_prep(const float* __restrict__ x,
                                              const float* __restrict__ Wt,
                                              const float* __restrict__ Wx,
                                              const float* __restrict__ bh) {
    __shared__ float xs[Cc][9];
    __shared__ float Wts[Cc][33];
    __shared__ float Wxs[Cc][33];
    __shared__ float bhs[Uu];
    __shared__ __half kts[Uu][10];

    int b  = blockIdx.x >> 7;
    int t0 = (blockIdx.x & 127) * 8;
    int tid = threadIdx.x, w = tid >> 5, lane = tid & 31;

    {
        int c = tid >> 3, tl = tid & 7;
        xs[c][tl] = x[(size_t)b * Cc * Tt + (size_t)c * Tt + t0 + tl];
    }
    for (int i = tid; i < Cc * Uu; i += 256) {
        int c = i >> 5, u = i & 31;
        Wts[c][u] = Wt[i];
        Wxs[c][u] = Wx[i];
    }
    if (tid < Uu) bhs[tid] = bh[tid];
    __syncthreads();

    {
        int tl = w, u = lane;
        float accq = bhs[u], acck = 0.f;
        #pragma unroll
        for (int c = 0; c < Cc; c++) {
            float xv = xs[c][tl];
            accq += xv * Wts[c][u];
            acck += xv * Wxs[c][u];
        }
        g_qp[((size_t)b * Tt + t0 + tl) * Uu + u] = accq;
        kts[u][tl] = __float2half(acck);
    }
    __syncthreads();

    if (tid < 128) {
        int r = tid >> 2, g = tid & 3;
        __half* kh = (__half*)g_kh_u;
        __half2 kv = __halves2half2(kts[r][2 * g], kts[r][2 * g + 1]);
        *(unsigned*)(kh + ((size_t)b * Uu + r) * Tt + t0 + 2 * g) = h22u(kv);
        __half* xh = (__half*)g_xh_u;
        __half2 xv = __floats2half2_rn(xs[r][2 * g], xs[r][2 * g + 1]);
        *(unsigned*)(xh + ((size_t)b * Cc + r) * Tt + t0 + 2 * g) = h22u(xv);
    }
}

// ---------------------------------------------------------------------------
// k_scores (R6/R8): hybrid MUFU/poly tanh, at joint FMA+MUFU roofline.
// ---------------------------------------------------------------------------
__global__ void __launch_bounds__(256, 3) k_scores(const float* __restrict__ Wa,
                                                   const float* __restrict__ ba) {
    __shared__ __half2 khs[Uu][PCH];   // 16KB
    __shared__ __half2 qsm2[8][33];

    int b  = blockIdx.x / (Tt / 8);
    int i0 = (blockIdx.x % (Tt / 8)) * 8;
    int tid = threadIdx.x, w = tid >> 5, lane = tid & 31;
    int i = i0 + w;
    size_t row = (size_t)b * Tt + i;

    qsm2[tid >> 5][tid & 31] =
        __float2half2_rn(g_qp[((size_t)b * Tt + i0 + (tid >> 5)) * Uu + (tid & 31)]);

    __half2 wa2[Uu];
    #pragma unroll
    for (int u = 0; u < Uu; u++) wa2[u] = __float2half2_rn(Wa[u]);
    __half2 ba2  = __float2half2_rn(ba[0]);
    __half2 m2   = __float2half2_rn(-60000.f);
    __half2 z2   = __float2half2_rn(0.f);
    __half2 one2 = __float2half2_rn(1.f);
    __half2 ca2  = __float2half2_rn(-1.f / 3.f);
    __half2 cb2  = __float2half2_rn(2.f / 15.f);

    const uint4* kb4 = (const uint4*)g_kh_u + (size_t)b * (Uu * Tt / 8);
    unsigned* erow = g_e_u + row * (Tt / 2);
    __syncthreads();

    for (int ch = 0; ch < NCH; ch++) {
        __syncthreads();
        #pragma unroll
        for (int k = 0; k < 4; k++) {
            int idx = tid + k * 256;
            int r = idx >> 5, g = idx & 31;
            ((uint4*)khs)[idx] = kb4[r * 128 + ch * 32 + g];
        }
        __syncthreads();

        #pragma unroll
        for (int jt = 0; jt < 4; jt++) {
            int pj = jt * 32 + lane;
            __half2 acc0 = z2, acc1 = z2;
            #pragma unroll
            for (int u = 0; u < Uu; u += 2) {
                __half2 xm = __hadd2(qsm2[w][u], khs[u][pj]);
                acc0 = __hfma2(wa2[u], tanh2(xm), acc0);
                __half2 xp = __hadd2(qsm2[w][u + 1], khs[u + 1][pj]);
                __half2 x2 = __hmul2(xp, xp);
                __half2 tp = __hfma2(x2, cb2, ca2);
                tp = __hfma2(x2, tp, one2);
                acc1 = __hfma2(wa2[u + 1], __hmul2(xp, tp), acc1);
            }
            __half2 e2 = __hadd2(__hadd2(acc0, acc1), ba2);
            m2 = __hmax2(m2, e2);
            erow[ch * PCH + pj] = h22u(e2);
        }
    }

    float m = fmaxf(__low2float(m2), __high2float(m2));
    #pragma unroll
    for (int off = 16; off; off >>= 1)
        m = fmaxf(m, __shfl_xor_sync(0xffffffffu, m, off));
    if (lane == 0) g_rm[row] = m;
}

// ---------------------------------------------------------------------------
// k_av_ff v2: 8 tokens/block, 128 threads, grid = B*(T/8) = 512 blocks.
// smem UNION: x-tile (phase 1) overlaps FF weights (phase 2) -> 39KB total.
// ---------------------------------------------------------------------------
#define OFF_XT    0                          // __half2 xh2s[Cc][256]  32768 B (phase 1)
#define OFF_W1T   0                          // float W1T[Cc*129]      16512 B (phase 2)
#define OFF_W2P   16512                      // float W2p[Cc*129]      16512 B (phase 2)
#define OFF_YS    33024                      // float ys[8*33]          1056 B
#define OFF_H1    34080                      // float h1s[8*132]        4224 B
#define OFF_B1    38304                      // float b1s[128]           512 B
#define OFF_B2    38816                      // float b2s[32]            128 B
#define OFF_G2    38944                      // float g2s[32]            128 B
#define OFF_BE2   39072                      // float be2s[32]           128 B
#define SMEM_AVFF 39200

__global__ void __launch_bounds__(128) k_av_ff(const float* __restrict__ x,
                                               float* __restrict__ a_out,
                                               const float* __restrict__ g1,
                                               const float* __restrict__ be1,
                                               const float* __restrict__ W1,
                                               const float* __restrict__ b1,
                                               const float* __restrict__ W2,
                                               const float* __restrict__ b2,
                                               const float* __restrict__ g2,
                                               const float* __restrict__ be2,
                                               float* __restrict__ y2) {
    extern __shared__ char dyn[];
    __half2 (*xh2s)[256] = (__half2 (*)[256])(dyn + OFF_XT);
    float* W1T  = (float*)(dyn + OFF_W1T);
    float* W2p  = (float*)(dyn + OFF_W2P);
    float* ys   = (float*)(dyn + OFF_YS);
    float* h1s  = (float*)(dyn + OFF_H1);
    float* b1s  = (float*)(dyn + OFF_B1);
    float* b2s  = (float*)(dyn + OFF_B2);
    float* g2s  = (float*)(dyn + OFF_G2);
    float* be2s = (float*)(dyn + OFF_BE2);

    int b  = blockIdx.x / (Tt / 8);
    int t0 = (blockIdx.x % (Tt / 8)) * 8;
    int tid = threadIdx.x, w = tid >> 5, lane = tid & 31;
    int tA = t0 + 2 * w, tB = tA + 1;
    size_t rowA = (size_t)b * Tt + tA, rowB = rowA + 1;

    // small persistent staging (biases) — safe region
    if (tid < Hh) b1s[tid] = b1[tid];
    if (tid < Cc) { b2s[tid] = b2[tid]; g2s[tid] = g2[tid]; be2s[tid] = be2[tid]; }

    const unsigned* eAu = g_e_u + rowA * (Tt / 2);
    const unsigned* eBu = g_e_u + rowB * (Tt / 2);
    const uint4* eA4 = (const uint4*)eAu;
    const uint4* eB4 = (const uint4*)eBu;

    float sA = 0.f, sB = 0.f;
    __half2 zero2 = __float2half2_rn(0.f);
    __half2 vA[Cc], vB[Cc];
    #pragma unroll
    for (int c = 0; c < Cc; c++) { vA[c] = zero2; vB[c] = zero2; }

    // ---- phase 1: attention-apply over 2 chunks of 512 j ----
    for (int chunk = 0; chunk < 2; chunk++) {
        __syncthreads();
        for (int idx = tid; idx < Cc * 64; idx += 128) {
            int c = idx >> 6, g = idx & 63;
            ((uint4*)xh2s)[c * 64 + g] =
                ((const uint4*)g_xh_u)[(size_t)b * Cc * Tt / 8 + c * 128 + chunk * 64 + g];
        }
        __syncthreads();

        #pragma unroll
        for (int q = 0; q < 2; q++) {
            int g   = chunk * 64 + q * 32 + lane;
            int lp4 = q * 32 + lane;
            uint4 ea = eA4[g], eb = eB4[g];
            unsigned eua[4] = {ea.x, ea.y, ea.z, ea.w};
            unsigned eub[4] = {eb.x, eb.y, eb.z, eb.w};
            __half2 pA[4], pB[4];
            #pragma unroll
            for (int r = 0; r < 4; r++) {
                float2 fa = __half22float2(u2h2(eua[r]));
                float2 fb = __half22float2(u2h2(eub[r]));
                float pax = __expf(fa.x), pay = __expf(fa.y);
                float pbx = __expf(fb.x), pby = __expf(fb.y);
                sA += pax + pay; sB += pbx + pby;
                pA[r] = __floats2half2_rn(pax, pay);
                pB[r] = __floats2half2_rn(pbx, pby);
            }
            #pragma unroll
            for (int c = 0; c < Cc; c++) {
                uint4 xv = ((const uint4*)&xh2s[c][0])[lp4];
                vA[c] = __hfma2(pA[0], u2h2(xv.x), vA[c]);
                vA[c] = __hfma2(pA[1], u2h2(xv.y), vA[c]);
                vA[c] = __hfma2(pA[2], u2h2(xv.z), vA[c]);
                vA[c] = __hfma2(pA[3], u2h2(xv.w), vA[c]);
                vB[c] = __hfma2(pB[0], u2h2(xv.x), vB[c]);
                vB[c] = __hfma2(pB[1], u2h2(xv.y), vB[c]);
                vB[c] = __hfma2(pB[2], u2h2(xv.z), vB[c]);
                vB[c] = __hfma2(pB[3], u2h2(xv.w), vB[c]);
            }
        }
    }
    __syncthreads();   // x-tile dead; its smem becomes the FF weight buffer

    // ---- phase 2 staging: FF weights into the union region ----
    for (int i = tid; i < Hh * Cc; i += 128) {
        int h = i >> 5, c = i & 31;
        W1T[c * 129 + h] = W1[i];                 // W1 (H,C) row-major
        int c2 = i >> 7, h2 = i & 127;
        W2p[c2 * 129 + h2] = W2[i];               // W2 (C,H) row-major
    }

    float vfA[Cc], vfB[Cc];
    #pragma unroll
    for (int c = 0; c < Cc; c++) {
        float2 fa = __half22float2(vA[c]); vfA[c] = fa.x + fa.y;
        float2 fb = __half22float2(vB[c]); vfB[c] = fb.x + fb.y;
    }

    #pragma unroll
    for (int off = 16; off; off >>= 1) {
        sA += __shfl_xor_sync(0xffffffffu, sA, off);
        sB += __shfl_xor_sync(0xffffffffu, sB, off);
    }
    float invA = 1.f / (sA + 1e-5f * __expf(g_rm[rowA]));
    float invB = 1.f / (sB + 1e-5f * __expf(g_rm[rowB]));

    float mineA = 0.f, mineB = 0.f;
    #pragma unroll
    for (int c = 0; c < Cc; c++) {
        float ta = vfA[c], tb = vfB[c];
        #pragma unroll
        for (int off = 16; off; off >>= 1) {
            ta += __shfl_xor_sync(0xffffffffu, ta, off);
            tb += __shfl_xor_sync(0xffffffffu, tb, off);
        }
        if (lane == c) { mineA = ta; mineB = tb; }
    }

    // ---- LN1 (lane = channel) -> ys ----
    const float* xb = x + (size_t)b * Cc * Tt + (size_t)lane * Tt;
    #pragma unroll
    for (int r = 0; r < 2; r++) {
        int t = (r == 0) ? tA : tB;
        float z = xb[t] + ((r == 0) ? mineA * invA : mineB * invB);
        float sum = z;
        #pragma unroll
        for (int off = 16; off; off >>= 1)
            sum += __shfl_xor_sync(0xffffffffu, sum, off);
        float mean = sum * (1.f / Cc);
        float d = z - mean;
        float vv = d * d;
        #pragma unroll
        for (int off = 16; off; off >>= 1)
            vv += __shfl_xor_sync(0xffffffffu, vv, off);
        float rstd = rsqrtf(vv * (1.f / Cc) + 1e-14f);
        ys[(2 * w + r) * 33 + lane] = d * rstd * g1[lane] + be1[lane];
    }
    __syncthreads();   // weights staged + ys ready

    // ---- FF (intra-warp, tokens 2w, 2w+1) ----
    int tokbase = 2 * w;
    float acc[4][2];
    #pragma unroll
    for (int k = 0; k < 4; k++) {
        float bb = b1s[lane + 32 * k];
        acc[k][0] = bb; acc[k][1] = bb;
    }
    #pragma unroll
    for (int c = 0; c < Cc; c++) {
        float yv0 = ys[tokbase * 33 + c];
        float yv1 = ys[(tokbase + 1) * 33 + c];
        #pragma unroll
        for (int k = 0; k < 4; k++) {
            float wv = W1T[c * 129 + lane + 32 * k];
            acc[k][0] += yv0 * wv;
            acc[k][1] += yv1 * wv;
        }
    }
    #pragma unroll
    for (int k = 0; k < 4; k++) {
        h1s[tokbase * 132 + lane + 32 * k]       = fmaxf(acc[k][0], 0.f);
        h1s[(tokbase + 1) * 132 + lane + 32 * k] = fmaxf(acc[k][1], 0.f);
    }
    __syncwarp();

    float a2[2] = {0.f, 0.f};
    #pragma unroll 4
    for (int h = 0; h < Hh; h++) {
        float wv = W2p[lane * 129 + h];
        a2[0] += h1s[tokbase * 132 + h] * wv;
        a2[1] += h1s[(tokbase + 1) * 132 + h] * wv;
    }

    #pragma unroll
    for (int tk = 0; tk < 2; tk++) {
        int tok = tokbase + tk;
        int t = t0 + tok;
        float z = ys[tok * 33 + lane] + a2[tk] + b2s[lane];
        float sum = z;
        #pragma unroll
        for (int off = 16; off; off >>= 1)
            sum += __shfl_xor_sync(0xffffffffu, sum, off);
        float mean = sum * (1.f / Cc);
        float d = z - mean;
        float vv = d * d;
        #pragma unroll
        for (int off = 16; off; off >>= 1)
            vv += __shfl_xor_sync(0xffffffffu, vv, off);
        float rstd = rsqrtf(vv * (1.f / Cc) + 1e-14f);
        y2[(size_t)b * Cc * Tt + (size_t)lane * Tt + t] = d * rstd * g2s[lane] + be2s[lane];
    }

    // ---- normalized-a write ----
    float* arowA = a_out + rowA * Tt;
    float* arowB = a_out + rowB * Tt;
    #pragma unroll
    for (int q = 0; q < 16; q++) {
        int idx = q * 32 + lane;
        float2 fa = __half22float2(u2h2(eAu[idx]));
        float2 fb = __half22float2(u2h2(eBu[idx]));
        ((float2*)arowA)[idx] = make_float2(__expf(fa.x) * invA, __expf(fa.y) * invA);
        ((float2*)arowB)[idx] = make_float2(__expf(fb.x) * invB, __expf(fb.y) * invB);
    }
}

// ---------------------------------------------------------------------------
extern "C" void kernel_launch(void* const* d_in, const int* in_sizes, int n_in,
                              void* d_out, int out_size) {
    (void)in_sizes; (void)n_in; (void)out_size;
    const float* x   = (const float*)d_in[0];
    const float* Wt  = (const float*)d_in[1];
    const float* Wx  = (const float*)d_in[2];
    const float* bh  = (const float*)d_in[3];
    const float* Wa  = (const float*)d_in[4];
    const float* ba  = (const float*)d_in[5];
    const float* g1  = (const float*)d_in[6];
    const float* be1 = (const float*)d_in[7];
    const float* W1  = (const float*)d_in[8];
    const float* b1  = (const float*)d_in[9];
    const float* W2  = (const float*)d_in[10];
    const float* b2  = (const float*)d_in[11];
    const float* g2  = (const float*)d_in[12];
    const float* be2 = (const float*)d_in[13];

    float* out = (float*)d_out;
    float* y2  = out;                    // (B,C,T) = 131072 floats
    float* a   = out + Bq * Cc * Tt;     // (B,T,T) = 4194304 floats

    cudaFuncSetAttribute(k_av_ff, cudaFuncAttributeMaxDynamicSharedMemorySize, SMEM_AVFF);

    k_prep  <<<Bq * (Tt / 8), 256>>>(x, Wt, Wx, bh);
    k_scores<<<Bq * (Tt / 8), 256>>>(Wa, ba);
    k_av_ff <<<Bq * (Tt / 8), 128, SMEM_AVFF>>>(x, a, g1, be1, W1, b1, W2, b2, g2, be2, y2);
}

// round 10
// speedup vs baseline: 1.1910x; 1.1330x over previous
#include <cuda_runtime.h>
#include <cuda_fp16.h>

#define Bq 4
#define Cc 32
#define Tt 1024
#define Uu 32
#define Hh 128
#define NCHK 4                  // 256-j chunks

// Scratch — device globals (no allocations allowed).
__device__ float    g_qp[Bq * Tt * Uu];            // q + bh, (B,T,U) f32
__device__ unsigned g_kh_u[Bq * Uu * Tt / 2];      // k as f16, (B,U,T)
__device__ unsigned g_xh_u[Bq * Cc * Tt / 2];      // x as f16, (B,C,T)

__device__ __forceinline__ __half2 tanh2(__half2 x) {
    unsigned xi = *reinterpret_cast<unsigned*>(&x), ri;
    asm("tanh.approx.f16x2 %0, %1;" : "=r"(ri) : "r"(xi));
    return *reinterpret_cast<__half2*>(&ri);
}
__device__ __forceinline__ __half2 u2h2(unsigned u) { return *reinterpret_cast<__half2*>(&u); }
__device__ __forceinline__ unsigned h22u(__half2 h) { return *reinterpret_cast<unsigned*>(&h); }

// ---------------------------------------------------------------------------
// k_prep (R8, proven): 8 tokens/block, grid = B*(T/8) = 512, 256 threads.
// ---------------------------------------------------------------------------
__global__ void __launch_bounds__(256) k_prep(const float* __restrict__ x,
                                              const float* __restrict__ Wt,
                                              const float* __restrict__ Wx,
                                              const float* __restrict__ bh) {
    __shared__ float xs[Cc][9];
    __shared__ float Wts[Cc][33];
    __shared__ float Wxs[Cc][33];
    __shared__ float bhs[Uu];
    __shared__ __half kts[Uu][10];

    int b  = blockIdx.x >> 7;
    int t0 = (blockIdx.x & 127) * 8;
    int tid = threadIdx.x, w = tid >> 5, lane = tid & 31;

    {
        int c = tid >> 3, tl = tid & 7;
        xs[c][tl] = x[(size_t)b * Cc * Tt + (size_t)c * Tt + t0 + tl];
    }
    for (int i = tid; i < Cc * Uu; i += 256) {
        int c = i >> 5, u = i & 31;
        Wts[c][u] = Wt[i];
        Wxs[c][u] = Wx[i];
    }
    if (tid < Uu) bhs[tid] = bh[tid];
    __syncthreads();

    {
        int tl = w, u = lane;
        float accq = bhs[u], acck = 0.f;
        #pragma unroll
        for (int c = 0; c < Cc; c++) {
            float xv = xs[c][tl];
            accq += xv * Wts[c][u];
            acck += xv * Wxs[c][u];
        }
        g_qp[((size_t)b * Tt + t0 + tl) * Uu + u] = accq;
        kts[u][tl] = __float2half(acck);
    }
    __syncthreads();

    if (tid < 128) {
        int r = tid >> 2, g = tid & 3;
        __half* kh = (__half*)g_kh_u;
        __half2 kv = __halves2half2(kts[r][2 * g], kts[r][2 * g + 1]);
        *(unsigned*)(kh + ((size_t)b * Uu + r) * Tt + t0 + 2 * g) = h22u(kv);
        __half* xh = (__half*)g_xh_u;
        __half2 xv = __floats2half2_rn(xs[r][2 * g], xs[r][2 * g + 1]);
        *(unsigned*)(xh + ((size_t)b * Cc + r) * Tt + t0 + 2 * g) = h22u(xv);
    }
}

// ---------------------------------------------------------------------------
// k_fused: scores + softmax + v + a-write + LN1 + FF + LN2, per 8 rows.
// e-tile lives in smem — no e global round-trip. grid = B*(T/8) = 512,
// 128 threads; warp w owns rows t0+2w, t0+2w+1.
// ---------------------------------------------------------------------------
#define OFF_K    0                           // half2 khs[32][128] 16384 | x-tile | W1T(0..16512)
#define OFF_E    16384                       // half2 es[8][512]   16384 | W2p(16512..33024)
#define OFF_WA   32768                       // half2 was[32]        128 (dead by FF)
#define OFF_Q    32896                       // float qsm[8*33]     1056 (dead by FF)
#define OFF_YS   33952                       // float ys[8*33]      1056
#define OFF_H1   35008                       // float h1s[8*132]    4224
#define OFF_B1   39232                       // float b1s[128]       512
#define OFF_B2   39744                       // float b2s[32]        128
#define OFF_G2   39872                       // float g2s[32]        128
#define OFF_BE2  40000                       // float be2s[32]       128
#define SMEM_FUSED 40128

__global__ void __launch_bounds__(128) k_fused(const float* __restrict__ x,
                                               float* __restrict__ a_out,
                                               const float* __restrict__ Wa,
                                               const float* __restrict__ ba,
                                               const float* __restrict__ g1,
                                               const float* __restrict__ be1,
                                               const float* __restrict__ W1,
                                               const float* __restrict__ b1,
                                               const float* __restrict__ W2,
                                               const float* __restrict__ b2,
                                               const float* __restrict__ g2,
                                               const float* __restrict__ be2,
                                               float* __restrict__ y2) {
    extern __shared__ char dyn[];
    __half2* khs  = (__half2*)(dyn + OFF_K);    // [32][128]
    __half2* es   = (__half2*)(dyn + OFF_E);    // [8][512]
    __half2* was  = (__half2*)(dyn + OFF_WA);
    float* qsm  = (float*)(dyn + OFF_Q);
    float* W1T  = (float*)(dyn + OFF_K);        // FF overlay
    float* W2p  = (float*)(dyn + OFF_K + 16512);
    float* ys   = (float*)(dyn + OFF_YS);
    float* h1s  = (float*)(dyn + OFF_H1);
    float* b1s  = (float*)(dyn + OFF_B1);
    float* b2s  = (float*)(dyn + OFF_B2);
    float* g2s  = (float*)(dyn + OFF_G2);
    float* be2s = (float*)(dyn + OFF_BE2);

    int b  = blockIdx.x >> 7;
    int t0 = (blockIdx.x & 127) * 8;
    int tid = threadIdx.x, w = tid >> 5, lane = tid & 31;
    int rA = 2 * w, rB = 2 * w + 1;
    int tA = t0 + rA, tB = t0 + rB;
    size_t rowA = (size_t)b * Tt + tA, rowB = (size_t)b * Tt + tB;

    // ---- staging ----
    for (int i = tid; i < 8 * Uu; i += 128) {
        int r = i >> 5, u = i & 31;
        qsm[r * 33 + u] = g_qp[((size_t)b * Tt + t0 + r) * Uu + u];
    }
    if (tid < Uu) was[tid] = __float2half2_rn(Wa[tid]);
    if (tid < Hh) b1s[tid] = b1[tid];
    if (tid < Cc) { b2s[tid] = b2[tid]; g2s[tid] = g2[tid]; be2s[tid] = be2[tid]; }
    __syncthreads();

    __half2 qA[Uu], qB[Uu];
    #pragma unroll
    for (int u = 0; u < Uu; u++) {
        qA[u] = __float2half2_rn(qsm[rA * 33 + u]);
        qB[u] = __float2half2_rn(qsm[rB * 33 + u]);
    }
    __half2 ba2  = __float2half2_rn(ba[0]);
    __half2 mA2  = __float2half2_rn(-60000.f), mB2 = mA2;
    __half2 z2   = __float2half2_rn(0.f);
    __half2 one2 = __float2half2_rn(1.f);
    __half2 ca2  = __float2half2_rn(-1.f / 3.f);
    __half2 cb2  = __float2half2_rn(2.f / 15.f);

    const uint4* kb4 = (const uint4*)g_kh_u + (size_t)b * (Uu * Tt / 8);

    // ---- Phase A: e for 8 rows, tile by tile, into smem es ----
    for (int ch = 0; ch < NCHK; ch++) {
        __syncthreads();
        #pragma unroll
        for (int k = 0; k < 8; k++) {
            int idx = tid + k * 128;
            int r = idx >> 5, g = idx & 31;
            ((uint4*)khs)[idx] = kb4[r * 128 + ch * 32 + g];
        }
        __syncthreads();

        #pragma unroll
        for (int jt = 0; jt < 4; jt++) {
            int pj = jt * 32 + lane;
            __half2 a0 = z2, a1 = z2, b0 = z2, b1h = z2;
            #pragma unroll
            for (int u = 0; u < Uu; u += 2) {
                __half2 k0 = khs[u * 128 + pj], k1 = khs[(u + 1) * 128 + pj];
                __half2 w0 = was[u], w1 = was[u + 1];
                // even u: MUFU tanh, both rows
                a0 = __hfma2(w0, tanh2(__hadd2(qA[u], k0)), a0);
                b0 = __hfma2(w0, tanh2(__hadd2(qB[u], k0)), b0);
                // odd u: poly, both rows
                __half2 xpA = __hadd2(qA[u + 1], k1);
                __half2 x2A = __hmul2(xpA, xpA);
                __half2 tpA = __hfma2(x2A, cb2, ca2);
                tpA = __hfma2(x2A, tpA, one2);
                a1 = __hfma2(w1, __hmul2(xpA, tpA), a1);
                __half2 xpB = __hadd2(qB[u + 1], k1);
                __half2 x2B = __hmul2(xpB, xpB);
                __half2 tpB = __hfma2(x2B, cb2, ca2);
                tpB = __hfma2(x2B, tpB, one2);
                b1h = __hfma2(w1, __hmul2(xpB, tpB), b1h);
            }
            __half2 eA2 = __hadd2(__hadd2(a0, a1), ba2);
            __half2 eB2 = __hadd2(__hadd2(b0, b1h), ba2);
            mA2 = __hmax2(mA2, eA2);
            mB2 = __hmax2(mB2, eB2);
            es[rA * 512 + ch * 128 + pj] = eA2;
            es[rB * 512 + ch * 128 + pj] = eB2;
        }
    }

    float mAv = fmaxf(__low2float(mA2), __high2float(mA2));
    float mBv = fmaxf(__low2float(mB2), __high2float(mB2));
    #pragma unroll
    for (int off = 16; off; off >>= 1) {
        mAv = fmaxf(mAv, __shfl_xor_sync(0xffffffffu, mAv, off));
        mBv = fmaxf(mBv, __shfl_xor_sync(0xffffffffu, mBv, off));
    }

    // ---- Phase B: s + unnormalized v (x-chunks overlay khs) ----
    float sA = 0.f, sB = 0.f;
    __half2 vA[Cc], vB[Cc];
    #pragma unroll
    for (int c = 0; c < Cc; c++) { vA[c] = z2; vB[c] = z2; }

    const uint4* xsrc = (const uint4*)g_xh_u + (size_t)b * (Cc * Tt / 8);
    __half2* xh2s = khs;   // overlay

    for (int ch = 0; ch < NCHK; ch++) {
        __syncthreads();
        #pragma unroll
        for (int k = 0; k < 8; k++) {
            int idx = tid + k * 128;
            int r = idx >> 5, g = idx & 31;
            ((uint4*)xh2s)[idx] = xsrc[r * 128 + ch * 32 + g];
        }
        __syncthreads();

        uint4 ea = ((const uint4*)(es + rA * 512))[ch * 32 + lane];
        uint4 eb = ((const uint4*)(es + rB * 512))[ch * 32 + lane];
        unsigned eua[4] = {ea.x, ea.y, ea.z, ea.w};
        unsigned eub[4] = {eb.x, eb.y, eb.z, eb.w};
        __half2 pA[4], pB[4];
        #pragma unroll
        for (int r = 0; r < 4; r++) {
            float2 fa = __half22float2(u2h2(eua[r]));
            float2 fb = __half22float2(u2h2(eub[r]));
            float pax = __expf(fa.x), pay = __expf(fa.y);
            float pbx = __expf(fb.x), pby = __expf(fb.y);
            sA += pax + pay; sB += pbx + pby;
            pA[r] = __floats2half2_rn(pax, pay);
            pB[r] = __floats2half2_rn(pbx, pby);
        }
        #pragma unroll
        for (int c = 0; c < Cc; c++) {
            uint4 xv = ((const uint4*)(xh2s + c * 128))[lane];
            vA[c] = __hfma2(pA[0], u2h2(xv.x), vA[c]);
            vA[c] = __hfma2(pA[1], u2h2(xv.y), vA[c]);
            vA[c] = __hfma2(pA[2], u2h2(xv.z), vA[c]);
            vA[c] = __hfma2(pA[3], u2h2(xv.w), vA[c]);
            vB[c] = __hfma2(pB[0], u2h2(xv.x), vB[c]);
            vB[c] = __hfma2(pB[1], u2h2(xv.y), vB[c]);
            vB[c] = __hfma2(pB[2], u2h2(xv.z), vB[c]);
            vB[c] = __hfma2(pB[3], u2h2(xv.w), vB[c]);
        }
    }

    float vfA[Cc], vfB[Cc];
    #pragma unroll
    for (int c = 0; c < Cc; c++) {
        float2 fa = __half22float2(vA[c]); vfA[c] = fa.x + fa.y;
        float2 fb = __half22float2(vB[c]); vfB[c] = fb.x + fb.y;
    }
    #pragma unroll
    for (int off = 16; off; off >>= 1) {
        sA += __shfl_xor_sync(0xffffffffu, sA, off);
        sB += __shfl_xor_sync(0xffffffffu, sB, off);
    }
    float invA = 1.f / (sA + 1e-5f * __expf(mAv));
    float invB = 1.f / (sB + 1e-5f * __expf(mBv));

    // ---- Phase C: normalized a straight from smem e ----
    {
        float* arowA = a_out + rowA * Tt;
        float* arowB = a_out + rowB * Tt;
        const unsigned* esA = (const unsigned*)(es + rA * 512);
        const unsigned* esB = (const unsigned*)(es + rB * 512);
        #pragma unroll
        for (int q = 0; q < 16; q++) {
            int idx = q * 32 + lane;
            float2 fa = __half22float2(u2h2(esA[idx]));
            float2 fb = __half22float2(u2h2(esB[idx]));
            ((float2*)arowA)[idx] = make_float2(__expf(fa.x) * invA, __expf(fa.y) * invA);
            ((float2*)arowB)[idx] = make_float2(__expf(fb.x) * invB, __expf(fb.y) * invB);
        }
    }

    float mineA = 0.f, mineB = 0.f;
    #pragma unroll
    for (int c = 0; c < Cc; c++) {
        float ta = vfA[c], tb = vfB[c];
        #pragma unroll
        for (int off = 16; off; off >>= 1) {
            ta += __shfl_xor_sync(0xffffffffu, ta, off);
            tb += __shfl_xor_sync(0xffffffffu, tb, off);
        }
        if (lane == c) { mineA = ta; mineB = tb; }
    }

    __syncthreads();   // es/khs dead -> FF weight overlay begins

    for (int i = tid; i < Hh * Cc; i += 128) {
        int h = i >> 5, c = i & 31;
        W1T[c * 129 + h] = W1[i];                 // W1 (H,C) row-major
        int c2 = i >> 7, h2 = i & 127;
        W2p[c2 * 129 + h2] = W2[i];               // W2 (C,H) row-major
    }

    // ---- LN1 (lane = channel) -> ys ----
    const float* xb = x + (size_t)b * Cc * Tt + (size_t)lane * Tt;
    #pragma unroll
    for (int r = 0; r < 2; r++) {
        int t = (r == 0) ? tA : tB;
        float z = xb[t] + ((r == 0) ? mineA * invA : mineB * invB);
        float sum = z;
        #pragma unroll
        for (int off = 16; off; off >>= 1)
            sum += __shfl_xor_sync(0xffffffffu, sum, off);
        float mean = sum * (1.f / Cc);
        float d = z - mean;
        float vv = d * d;
        #pragma unroll
        for (int off = 16; off; off >>= 1)
            vv += __shfl_xor_sync(0xffffffffu, vv, off);
        float rstd = rsqrtf(vv * (1.f / Cc) + 1e-14f);
        ys[(2 * w + r) * 33 + lane] = d * rstd * g1[lane] + be1[lane];
    }
    __syncthreads();   // weights staged + ys ready

    // ---- FF (intra-warp, tokens 2w, 2w+1) ----
    int tokbase = 2 * w;
    float acc[4][2];
    #pragma unroll
    for (int k = 0; k < 4; k++) {
        float bb = b1s[lane + 32 * k];
        acc[k][0] = bb; acc[k][1] = bb;
    }
    #pragma unroll
    for (int c = 0; c < Cc; c++) {
        float yv0 = ys[tokbase * 33 + c];
        float yv1 = ys[(tokbase + 1) * 33 + c];
        #pragma unroll
        for (int k = 0; k < 4; k++) {
            float wv = W1T[c * 129 + lane + 32 * k];
            acc[k][0] += yv0 * wv;
            acc[k][1] += yv1 * wv;
        }
    }
    #pragma unroll
    for (int k = 0; k < 4; k++) {
        h1s[tokbase * 132 + lane + 32 * k]       = fmaxf(acc[k][0], 0.f);
        h1s[(tokbase + 1) * 132 + lane + 32 * k] = fmaxf(acc[k][1], 0.f);
    }
    __syncwarp();

    float a2[2] = {0.f, 0.f};
    #pragma unroll 4
    for (int h = 0; h < Hh; h++) {
        float wv = W2p[lane * 129 + h];
        a2[0] += h1s[tokbase * 132 + h] * wv;
        a2[1] += h1s[(tokbase + 1) * 132 + h] * wv;
    }

    #pragma unroll
    for (int tk = 0; tk < 2; tk++) {
        int tok = tokbase + tk;
        int t = t0 + tok;
        float z = ys[tok * 33 + lane] + a2[tk] + b2s[lane];
        float sum = z;
        #pragma unroll
        for (int off = 16; off; off >>= 1)
            sum += __shfl_xor_sync(0xffffffffu, sum, off);
        float mean = sum * (1.f / Cc);
        float d = z - mean;
        float vv = d * d;
        #pragma unroll
        for (int off = 16; off; off >>= 1)
            vv += __shfl_xor_sync(0xffffffffu, vv, off);
        float rstd = rsqrtf(vv * (1.f / Cc) + 1e-14f);
        y2[(size_t)b * Cc * Tt + (size_t)lane * Tt + t] = d * rstd * g2s[lane] + be2s[lane];
    }
}

// ---------------------------------------------------------------------------
extern "C" void kernel_launch(void* const* d_in, const int* in_sizes, int n_in,
                              void* d_out, int out_size) {
    (void)in_sizes; (void)n_in; (void)out_size;
    const float* x   = (const float*)d_in[0];
    const float* Wt  = (const float*)d_in[1];
    const float* Wx  = (const float*)d_in[2];
    const float* bh  = (const float*)d_in[3];
    const float* Wa  = (const float*)d_in[4];
    const float* ba  = (const float*)d_in[5];
    const float* g1  = (const float*)d_in[6];
    const float* be1 = (const float*)d_in[7];
    const float* W1  = (const float*)d_in[8];
    const float* b1  = (const float*)d_in[9];
    const float* W2  = (const float*)d_in[10];
    const float* b2  = (const float*)d_in[11];
    const float* g2  = (const float*)d_in[12];
    const float* be2 = (const float*)d_in[13];

    float* out = (float*)d_out;
    float* y2  = out;                    // (B,C,T) = 131072 floats
    float* a   = out + Bq * Cc * Tt;     // (B,T,T) = 4194304 floats

    cudaFuncSetAttribute(k_fused, cudaFuncAttributeMaxDynamicSharedMemorySize, SMEM_FUSED);

    k_prep <<<Bq * (Tt / 8), 256>>>(x, Wt, Wx, bh);
    k_fused<<<Bq * (Tt / 8), 128, SMEM_FUSED>>>(x, a, Wa, ba, g1, be1,
                                                W1, b1, W2, b2, g2, be2, y2);
}